// round 2
// baseline (speedup 1.0000x reference)
#include <cuda_runtime.h>
#include <cuda_bf16.h>
#include <math.h>

// ---------------------------------------------------------------------------
// GraphSAGE (2x SAGEConv mean) + WeightedSumAndMax readout + 2-layer MLP.
//
// Pipeline (all on default stream, graph-capturable, no allocations):
//   1. zero_scratch           : agg1, agg2, deg = 0
//   2. pad_kernel             : X[100000x74] -> Xpad[100000x76] (float4-aligned rows)
//   3. scatter (layer 1)      : warp/edge, red.global.add.v4.f32 into agg1 + deg
//   4. fused GEMM (layer 1)   : h1 = relu(X@Ws1 + (agg1/deg)@Wn1 + b1)
//   5. scatter (layer 2)      : agg2 += h1[src]
//   6. fused GEMM (layer 2)   : h2 = relu(h1@Ws2 + (agg2/deg)@Wn2 + b2)
//   7. wnode                  : w[n] = sigmoid(h2[n]. w_atom + b_atom)
//   8. readout                : block/graph, binary-search segment bounds (sorted
//                               graph_ids), per-dim weighted sum + max, no atomics
//   9. mlp                    : out[g] = (gfeat@Wp1 + bp1)@Wp2 + bp2
//
// R1 fix: ALL float4 / red.v4 targets must be 16B-aligned. Shared array a_s
// (1650 floats = 6600B) previously pushed w_s to an 8B-aligned address ->
// guaranteed misaligned float4 load. Now every vector-accessed array carries
// __align__(16) and shared sizes are padded to 16B multiples.
// ---------------------------------------------------------------------------

#define N_MAX   100000
#define FPAD    76          // 74 padded to 76 -> 19 float4 per row
#define HIDDEN  100         // 25 float4 per row
#define G_MAX   1024

// Scratch (static __device__ arrays: allocation-free per harness rules)
__device__ __align__(128) float d_Xpad [N_MAX * FPAD];
__device__ __align__(128) float d_agg1 [N_MAX * FPAD];
__device__ __align__(128) float d_deg  [N_MAX];
__device__ __align__(128) float d_h1   [N_MAX * HIDDEN];
__device__ __align__(128) float d_agg2 [N_MAX * HIDDEN];
__device__ __align__(128) float d_h2   [N_MAX * HIDDEN];
__device__ __align__(128) float d_wnode[N_MAX];
__device__ __align__(128) float d_gfeat[G_MAX * 2 * HIDDEN];

// ---------------------------------------------------------------------------
__device__ __forceinline__ void red_add_v4(float* p, float4 v) {
    asm volatile("red.global.add.v4.f32 [%0], {%1,%2,%3,%4};"
                 :: "l"(p), "f"(v.x), "f"(v.y), "f"(v.z), "f"(v.w) : "memory");
}

// ---------------------------------------------------------------------------
__global__ void zero_scratch(int N) {
    int i = blockIdx.x * blockDim.x + threadIdx.x;
    int stride = gridDim.x * blockDim.x;
    int n1 = N * FPAD;
    for (int idx = i; idx < n1; idx += stride) d_agg1[idx] = 0.0f;
    int n2 = N * HIDDEN;
    for (int idx = i; idx < n2; idx += stride) d_agg2[idx] = 0.0f;
    for (int idx = i; idx < N;  idx += stride) d_deg[idx]  = 0.0f;
}

__global__ void pad_kernel(const float* __restrict__ X, int N, int inF) {
    int i = blockIdx.x * blockDim.x + threadIdx.x;
    int stride = gridDim.x * blockDim.x;
    int total = N * FPAD;
    for (int idx = i; idx < total; idx += stride) {
        int n = idx / FPAD;
        int k = idx - n * FPAD;
        d_Xpad[idx] = (k < inF) ? X[(size_t)n * inF + k] : 0.0f;
    }
}

// Layer-1 scatter: warp per edge, 19 float4 lanes + deg on lane 19.
__global__ void scatter1_kernel(const int* __restrict__ src,
                                const int* __restrict__ dst, int E) {
    int gid  = blockIdx.x * blockDim.x + threadIdx.x;
    int e    = gid >> 5;
    int lane = gid & 31;
    if (e >= E) return;
    int s = src[e];
    int d = dst[e];
    if (lane < FPAD / 4) {
        const float4 v = reinterpret_cast<const float4*>(d_Xpad)[(size_t)s * (FPAD/4) + lane];
        float* p = d_agg1 + (size_t)d * FPAD + lane * 4;
        red_add_v4(p, v);
    } else if (lane == FPAD / 4) {
        atomicAdd(&d_deg[d], 1.0f);
    }
}

// Layer-2 scatter: warp per edge, 25 float4 lanes over h1 rows.
__global__ void scatter2_kernel(const int* __restrict__ src,
                                const int* __restrict__ dst, int E) {
    int gid  = blockIdx.x * blockDim.x + threadIdx.x;
    int e    = gid >> 5;
    int lane = gid & 31;
    if (e >= E) return;
    int s = src[e];
    int d = dst[e];
    if (lane < HIDDEN / 4) {
        const float4 v = reinterpret_cast<const float4*>(d_h1)[(size_t)s * (HIDDEN/4) + lane];
        float* p = d_agg2 + (size_t)d * HIDDEN + lane * 4;
        red_add_v4(p, v);
    }
}

// ---------------------------------------------------------------------------
// Fused SAGE layer GEMM:
//   out[n][c] = relu( sum_k A[n][k] * Wcat[k][c] + b[c] )
//   A = concat(Xself_row, agg_row * 1/max(deg,1)), Wcat = [Wself; Wneigh]
// Register-blocked: 4 nodes x 4 cols per thread; 200 compute threads cover a
// 32-node x 100-col tile; K staged in chunks of 50 through shared memory.
// ---------------------------------------------------------------------------
#define KC  50
#define BM  32
#define ASZ (KC * (BM + 1) + 2)   // 1652 floats = 6608B: keeps following arrays 16B-aligned

__global__ __launch_bounds__(256, 4)
void sage_gemm_kernel(int layer, int N, int Fs, int Fn,
                      const float* __restrict__ Wself,
                      const float* __restrict__ Wneigh,
                      const float* __restrict__ bias) {
    __shared__ __align__(16) float w_s[KC * HIDDEN];     // [kl][c] (float4-read!)
    __shared__ __align__(16) float a_s[ASZ];             // [kl][n], padded rows
    __shared__ __align__(16) float invd_s[BM];

    const float* Xs  = (layer == 0) ? d_Xpad : d_h1;
    const float* Agg = (layer == 0) ? d_agg1 : d_agg2;
    float*       Out = (layer == 0) ? d_h1   : d_h2;
    const int    ldS = (layer == 0) ? FPAD   : HIDDEN;
    const int    ldA = ldS;

    const int tid  = threadIdx.x;
    const int base = blockIdx.x * BM;
    const int Ktot = Fs + Fn;
    const int nchunks = (Ktot + KC - 1) / KC;

    if (tid < BM) {
        int n = base + tid;
        float dg = (n < N) ? d_deg[n] : 1.0f;
        invd_s[tid] = 1.0f / fmaxf(dg, 1.0f);
    }
    __syncthreads();

    // thread -> 4x4 register tile
    const int cg = tid % 25;          // col group: cols 4*cg .. 4*cg+3
    const int ng = tid / 25;          // node group: nodes 4*ng .. 4*ng+3  (ng<8 for tid<200)
    float acc[4][4];
    #pragma unroll
    for (int i = 0; i < 4; i++)
        #pragma unroll
        for (int j = 0; j < 4; j++) acc[i][j] = 0.0f;

    for (int ch = 0; ch < nchunks; ch++) {
        int k0 = ch * KC;

        // stage A^T chunk: a_s[kl][n]
        for (int idx = tid; idx < KC * BM; idx += 256) {
            int n  = idx / KC;
            int kl = idx - n * KC;
            int kg = k0 + kl;
            int gn = base + n;
            float v = 0.0f;
            if (gn < N) {
                if (kg < Fs)        v = Xs[(size_t)gn * ldS + kg];
                else if (kg < Ktot) v = Agg[(size_t)gn * ldA + (kg - Fs)] * invd_s[n];
            }
            a_s[kl * (BM + 1) + n] = v;
        }
        // stage W chunk: w_s[kl][c]
        for (int idx = tid; idx < KC * HIDDEN; idx += 256) {
            int kl = idx / HIDDEN;
            int c  = idx - kl * HIDDEN;
            int kg = k0 + kl;
            float v = 0.0f;
            if (kg < Fs)        v = Wself[kg * HIDDEN + c];
            else if (kg < Ktot) v = Wneigh[(kg - Fs) * HIDDEN + c];
            w_s[kl * HIDDEN + c] = v;
        }
        __syncthreads();

        if (tid < 200) {
            #pragma unroll 2
            for (int kl = 0; kl < KC; kl++) {
                float4 w4 = *reinterpret_cast<const float4*>(&w_s[kl * HIDDEN + 4 * cg]);
                float a0 = a_s[kl * (BM + 1) + 4 * ng + 0];
                float a1 = a_s[kl * (BM + 1) + 4 * ng + 1];
                float a2 = a_s[kl * (BM + 1) + 4 * ng + 2];
                float a3 = a_s[kl * (BM + 1) + 4 * ng + 3];
                acc[0][0] += a0 * w4.x; acc[0][1] += a0 * w4.y; acc[0][2] += a0 * w4.z; acc[0][3] += a0 * w4.w;
                acc[1][0] += a1 * w4.x; acc[1][1] += a1 * w4.y; acc[1][2] += a1 * w4.z; acc[1][3] += a1 * w4.w;
                acc[2][0] += a2 * w4.x; acc[2][1] += a2 * w4.y; acc[2][2] += a2 * w4.z; acc[2][3] += a2 * w4.w;
                acc[3][0] += a3 * w4.x; acc[3][1] += a3 * w4.y; acc[3][2] += a3 * w4.z; acc[3][3] += a3 * w4.w;
            }
        }
        __syncthreads();
    }

    if (tid < 200) {
        float b[4];
        #pragma unroll
        for (int j = 0; j < 4; j++) b[j] = bias[4 * cg + j];
        #pragma unroll
        for (int i = 0; i < 4; i++) {
            int n = base + 4 * ng + i;
            if (n < N) {
                #pragma unroll
                for (int j = 0; j < 4; j++)
                    Out[(size_t)n * HIDDEN + 4 * cg + j] = fmaxf(acc[i][j] + b[j], 0.0f);
            }
        }
    }
}

// ---------------------------------------------------------------------------
// w[n] = sigmoid(h2[n] . w_atom + b_atom) — warp per node
__global__ void wnode_kernel(const float* __restrict__ w_atom,
                             const float* __restrict__ b_atom, int N) {
    int gid  = blockIdx.x * blockDim.x + threadIdx.x;
    int n    = gid >> 5;
    int lane = gid & 31;
    if (n >= N) return;
    float s = 0.0f;
    for (int k = lane; k < HIDDEN; k += 32)
        s += d_h2[(size_t)n * HIDDEN + k] * w_atom[k];
    #pragma unroll
    for (int o = 16; o; o >>= 1) s += __shfl_xor_sync(0xFFFFFFFFu, s, o);
    if (lane == 0) d_wnode[n] = 1.0f / (1.0f + expf(-(s + b_atom[0])));
}

// ---------------------------------------------------------------------------
__device__ __forceinline__ int lower_bound_i(const int* __restrict__ a, int n, int key) {
    int lo = 0, hi = n;
    while (lo < hi) {
        int m = (lo + hi) >> 1;
        if (a[m] < key) lo = m + 1; else hi = m;
    }
    return lo;
}

// block per graph; graph_ids sorted -> segment = [lb(g), lb(g+1))
__global__ void readout_kernel(const int* __restrict__ gids, int N) {
    int g = blockIdx.x;
    int t = threadIdx.x;
    int start = lower_bound_i(gids, N, g);
    int end   = lower_bound_i(gids, N, g + 1);
    if (t < HIDDEN) {
        float s = 0.0f;
        float m = 0.0f;   // relu output >= 0; empty graph -> 0 per reference
        for (int n = start; n < end; n++) {
            float v = d_h2[(size_t)n * HIDDEN + t];
            s += v * d_wnode[n];
            m = fmaxf(m, v);
        }
        d_gfeat[g * (2 * HIDDEN) + t]          = s;
        d_gfeat[g * (2 * HIDDEN) + HIDDEN + t] = m;
    }
}

// ---------------------------------------------------------------------------
// out[g] = (gfeat @ Wp1 + bp1) @ Wp2 + bp2   (64 hidden, no activation)
__global__ void mlp_kernel(const float* __restrict__ Wp1,
                           const float* __restrict__ bp1,
                           const float* __restrict__ Wp2,
                           const float* __restrict__ bp2,
                           float* __restrict__ out) {
    __shared__ float gf[2 * HIDDEN];
    __shared__ float partial[2];
    int g = blockIdx.x;
    int t = threadIdx.x;   // 64 threads
    for (int i = t; i < 2 * HIDDEN; i += 64) gf[i] = d_gfeat[g * (2 * HIDDEN) + i];
    __syncthreads();
    float acc = bp1[t];
    #pragma unroll 4
    for (int k = 0; k < 2 * HIDDEN; k++) acc += gf[k] * Wp1[k * 64 + t];
    float val = acc * Wp2[t];
    #pragma unroll
    for (int o = 16; o; o >>= 1) val += __shfl_xor_sync(0xFFFFFFFFu, val, o);
    if ((t & 31) == 0) partial[t >> 5] = val;
    __syncthreads();
    if (t == 0) out[g] = partial[0] + partial[1] + bp2[0];
}

// ---------------------------------------------------------------------------
extern "C" void kernel_launch(void* const* d_in, const int* in_sizes, int n_in,
                              void* d_out, int out_size) {
    const float* X    = (const float*)d_in[0];
    const int*   src  = (const int*)  d_in[1];
    const int*   dst  = (const int*)  d_in[2];
    const int*   gids = (const int*)  d_in[3];
    // d_in[4] = n_graphs (device scalar, unused; G = out_size)
    const float* Ws1 = (const float*)d_in[5];
    const float* Wn1 = (const float*)d_in[6];
    const float* b1  = (const float*)d_in[7];
    const float* Ws2 = (const float*)d_in[8];
    const float* Wn2 = (const float*)d_in[9];
    const float* b2  = (const float*)d_in[10];
    const float* wa  = (const float*)d_in[11];
    const float* ba  = (const float*)d_in[12];
    const float* Wp1 = (const float*)d_in[13];
    const float* bp1 = (const float*)d_in[14];
    const float* Wp2 = (const float*)d_in[15];
    const float* bp2 = (const float*)d_in[16];
    float* out = (float*)d_out;

    const int N   = in_sizes[3];
    const int E   = in_sizes[1];
    const int inF = in_sizes[0] / N;   // 74
    const int G   = out_size;          // 1024

    // 1. zero scratch
    zero_scratch<<<2048, 256>>>(N);
    // 2. pad X rows to float4 alignment
    pad_kernel<<<2048, 256>>>(X, N, inF);
    // 3. layer-1 edge aggregation (+degree)
    {
        long long threads = (long long)E * 32;
        int blocks = (int)((threads + 255) / 256);
        scatter1_kernel<<<blocks, 256>>>(src, dst, E);
    }
    // 4. layer-1 fused GEMM
    sage_gemm_kernel<<<(N + BM - 1) / BM, 256>>>(0, N, inF, inF, Ws1, Wn1, b1);
    // 5. layer-2 edge aggregation
    {
        long long threads = (long long)E * 32;
        int blocks = (int)((threads + 255) / 256);
        scatter2_kernel<<<blocks, 256>>>(src, dst, E);
    }
    // 6. layer-2 fused GEMM
    sage_gemm_kernel<<<(N + BM - 1) / BM, 256>>>(1, N, HIDDEN, HIDDEN, Ws2, Wn2, b2);
    // 7. per-node sigmoid gate
    {
        long long threads = (long long)N * 32;
        int blocks = (int)((threads + 255) / 256);
        wnode_kernel<<<blocks, 256>>>(wa, ba, N);
    }
    // 8. per-graph weighted sum + max
    readout_kernel<<<G, 128>>>(gids, N);
    // 9. predictor MLP
    mlp_kernel<<<G, 64>>>(Wp1, bp1, Wp2, bp2, out);
}

// round 4
// speedup vs baseline: 1.1858x; 1.1858x over previous
#include <cuda_runtime.h>
#include <cuda_bf16.h>
#include <math.h>

// ---------------------------------------------------------------------------
// GraphSAGE (2x SAGEConv mean) + WeightedSumAndMax readout + 2-layer MLP.
//
// R2/R3 changes (GEMM only; R3 resubmit after infra timeout):
//  - BM 32->40, thread tile 4x4, 250/256 threads compute (was 200/256)
//  - a_s row stride 44 floats (176B, 16B multiple) -> A operand is one LDS.128
//  - KC 50->25 (smem ~14.6KB) + __launch_bounds__(256,6) -> 6 blocks/SM, 75% occ
//  - compile-time strides in the inner loop to kill address-ALU traffic
// Pending prediction: gemm2 230 -> ~140us, total 938 -> ~770us.
// ---------------------------------------------------------------------------

#define N_MAX   100000
#define FPAD    76          // 74 padded to 76 -> 19 float4 per row
#define HIDDEN  100         // 25 float4 per row
#define G_MAX   1024

__device__ __align__(128) float d_Xpad [N_MAX * FPAD];
__device__ __align__(128) float d_agg1 [N_MAX * FPAD];
__device__ __align__(128) float d_deg  [N_MAX];
__device__ __align__(128) float d_h1   [N_MAX * HIDDEN];
__device__ __align__(128) float d_agg2 [N_MAX * HIDDEN];
__device__ __align__(128) float d_h2   [N_MAX * HIDDEN];
__device__ __align__(128) float d_wnode[N_MAX];
__device__ __align__(128) float d_gfeat[G_MAX * 2 * HIDDEN];

// ---------------------------------------------------------------------------
__device__ __forceinline__ void red_add_v4(float* p, float4 v) {
    asm volatile("red.global.add.v4.f32 [%0], {%1,%2,%3,%4};"
                 :: "l"(p), "f"(v.x), "f"(v.y), "f"(v.z), "f"(v.w) : "memory");
}

// ---------------------------------------------------------------------------
__global__ void zero_scratch(int N) {
    int i = blockIdx.x * blockDim.x + threadIdx.x;
    int stride = gridDim.x * blockDim.x;
    int n1 = N * FPAD;
    for (int idx = i; idx < n1; idx += stride) d_agg1[idx] = 0.0f;
    int n2 = N * HIDDEN;
    for (int idx = i; idx < n2; idx += stride) d_agg2[idx] = 0.0f;
    for (int idx = i; idx < N;  idx += stride) d_deg[idx]  = 0.0f;
}

__global__ void pad_kernel(const float* __restrict__ X, int N, int inF) {
    int i = blockIdx.x * blockDim.x + threadIdx.x;
    int stride = gridDim.x * blockDim.x;
    int total = N * FPAD;
    for (int idx = i; idx < total; idx += stride) {
        int n = idx / FPAD;
        int k = idx - n * FPAD;
        d_Xpad[idx] = (k < inF) ? X[(size_t)n * inF + k] : 0.0f;
    }
}

// Layer-1 scatter: warp per edge, 19 float4 lanes + deg on lane 19.
__global__ void scatter1_kernel(const int* __restrict__ src,
                                const int* __restrict__ dst, int E) {
    int gid  = blockIdx.x * blockDim.x + threadIdx.x;
    int e    = gid >> 5;
    int lane = gid & 31;
    if (e >= E) return;
    int s = src[e];
    int d = dst[e];
    if (lane < FPAD / 4) {
        const float4 v = reinterpret_cast<const float4*>(d_Xpad)[(size_t)s * (FPAD/4) + lane];
        float* p = d_agg1 + (size_t)d * FPAD + lane * 4;
        red_add_v4(p, v);
    } else if (lane == FPAD / 4) {
        atomicAdd(&d_deg[d], 1.0f);
    }
}

// Layer-2 scatter: warp per edge, 25 float4 lanes over h1 rows.
__global__ void scatter2_kernel(const int* __restrict__ src,
                                const int* __restrict__ dst, int E) {
    int gid  = blockIdx.x * blockDim.x + threadIdx.x;
    int e    = gid >> 5;
    int lane = gid & 31;
    if (e >= E) return;
    int s = src[e];
    int d = dst[e];
    if (lane < HIDDEN / 4) {
        const float4 v = reinterpret_cast<const float4*>(d_h1)[(size_t)s * (HIDDEN/4) + lane];
        float* p = d_agg2 + (size_t)d * HIDDEN + lane * 4;
        red_add_v4(p, v);
    }
}

// ---------------------------------------------------------------------------
// Fused SAGE layer GEMM:
//   out[n][c] = relu( sum_k A[n][k] * Wcat[k][c] + b[c] )
//   A = concat(Xself_row, agg_row * 1/max(deg,1)), Wcat = [Wself; Wneigh]
// BM=40 nodes x 100 cols per block; 250 threads each own a 4-node x 4-col tile.
// Inner loop per k: 1 LDS.128 (A, 4 nodes) + 1 LDS.128 (W, 4 cols) + 16 FFMA.
// ---------------------------------------------------------------------------
#define KC   25
#define BM   40
#define AST  44   // a_s row stride in floats: 176B = 16B multiple (vector loads ok)

__global__ __launch_bounds__(256, 6)
void sage_gemm_kernel(int layer, int N, int Fs, int Fn,
                      const float* __restrict__ Wself,
                      const float* __restrict__ Wneigh,
                      const float* __restrict__ bias) {
    __shared__ __align__(16) float w_s[KC * HIDDEN];   // [kl][c]  25x100
    __shared__ __align__(16) float a_s[KC * AST];      // [kl][n]  25x44 (40 used)
    __shared__ __align__(16) float invd_s[BM];

    const float* Xs  = (layer == 0) ? d_Xpad : d_h1;
    const float* Agg = (layer == 0) ? d_agg1 : d_agg2;
    float*       Out = (layer == 0) ? d_h1   : d_h2;
    const int    ldS = (layer == 0) ? FPAD   : HIDDEN;

    const int tid  = threadIdx.x;
    const int base = blockIdx.x * BM;
    const int Ktot = Fs + Fn;
    const int nchunks = (Ktot + KC - 1) / KC;

    if (tid < BM) {
        int n = base + tid;
        float dg = (n < N) ? d_deg[n] : 1.0f;
        invd_s[tid] = 1.0f / fmaxf(dg, 1.0f);
    }
    __syncthreads();

    // thread -> 4x4 register tile (250 compute threads)
    const int cg = tid % 25;          // cols 4*cg .. 4*cg+3
    const int ng = tid / 25;          // nodes 4*ng .. 4*ng+3 (ng<10 for tid<250)
    const bool active = (tid < 250);

    float acc[4][4];
    #pragma unroll
    for (int i = 0; i < 4; i++)
        #pragma unroll
        for (int j = 0; j < 4; j++) acc[i][j] = 0.0f;

    const float4* a4p = reinterpret_cast<const float4*>(a_s) + ng;   // + kl*(AST/4)
    const float4* w4p = reinterpret_cast<const float4*>(w_s) + cg;   // + kl*25

    for (int ch = 0; ch < nchunks; ch++) {
        int k0 = ch * KC;

        // stage A^T chunk: a_s[kl][n]  (KC*BM = 1000 elems, 4 passes)
        for (int idx = tid; idx < KC * BM; idx += 256) {
            int n  = idx / KC;
            int kl = idx - n * KC;
            int kg = k0 + kl;
            int gn = base + n;
            float v = 0.0f;
            if (gn < N) {
                if (kg < Fs)        v = Xs[(size_t)gn * ldS + kg];
                else if (kg < Ktot) v = Agg[(size_t)gn * ldS + (kg - Fs)] * invd_s[n];
            }
            a_s[kl * AST + n] = v;
        }
        // stage W chunk: w_s[kl][c]  (KC*100 = 2500 elems, 10 passes)
        for (int idx = tid; idx < KC * HIDDEN; idx += 256) {
            int kl = idx / HIDDEN;
            int c  = idx - kl * HIDDEN;
            int kg = k0 + kl;
            float v = 0.0f;
            if (kg < Fs)        v = Wself[kg * HIDDEN + c];
            else if (kg < Ktot) v = Wneigh[(kg - Fs) * HIDDEN + c];
            w_s[idx] = v;
        }
        __syncthreads();

        if (active) {
            #pragma unroll 5
            for (int kl = 0; kl < KC; kl++) {
                float4 a4 = a4p[kl * (AST / 4)];
                float4 w4 = w4p[kl * (HIDDEN / 4)];
                acc[0][0] += a4.x * w4.x; acc[0][1] += a4.x * w4.y; acc[0][2] += a4.x * w4.z; acc[0][3] += a4.x * w4.w;
                acc[1][0] += a4.y * w4.x; acc[1][1] += a4.y * w4.y; acc[1][2] += a4.y * w4.z; acc[1][3] += a4.y * w4.w;
                acc[2][0] += a4.z * w4.x; acc[2][1] += a4.z * w4.y; acc[2][2] += a4.z * w4.z; acc[2][3] += a4.z * w4.w;
                acc[3][0] += a4.w * w4.x; acc[3][1] += a4.w * w4.y; acc[3][2] += a4.w * w4.z; acc[3][3] += a4.w * w4.w;
            }
        }
        __syncthreads();
    }

    if (active) {
        float b[4];
        #pragma unroll
        for (int j = 0; j < 4; j++) b[j] = bias[4 * cg + j];
        #pragma unroll
        for (int i = 0; i < 4; i++) {
            int n = base + 4 * ng + i;
            if (n < N) {
                float4 o;
                o.x = fmaxf(acc[i][0] + b[0], 0.0f);
                o.y = fmaxf(acc[i][1] + b[1], 0.0f);
                o.z = fmaxf(acc[i][2] + b[2], 0.0f);
                o.w = fmaxf(acc[i][3] + b[3], 0.0f);
                reinterpret_cast<float4*>(Out + (size_t)n * HIDDEN)[cg] = o;
            }
        }
    }
}

// ---------------------------------------------------------------------------
// w[n] = sigmoid(h2[n] . w_atom + b_atom) — warp per node
__global__ void wnode_kernel(const float* __restrict__ w_atom,
                             const float* __restrict__ b_atom, int N) {
    int gid  = blockIdx.x * blockDim.x + threadIdx.x;
    int n    = gid >> 5;
    int lane = gid & 31;
    if (n >= N) return;
    float s = 0.0f;
    for (int k = lane; k < HIDDEN; k += 32)
        s += d_h2[(size_t)n * HIDDEN + k] * w_atom[k];
    #pragma unroll
    for (int o = 16; o; o >>= 1) s += __shfl_xor_sync(0xFFFFFFFFu, s, o);
    if (lane == 0) d_wnode[n] = 1.0f / (1.0f + expf(-(s + b_atom[0])));
}

// ---------------------------------------------------------------------------
__device__ __forceinline__ int lower_bound_i(const int* __restrict__ a, int n, int key) {
    int lo = 0, hi = n;
    while (lo < hi) {
        int m = (lo + hi) >> 1;
        if (a[m] < key) lo = m + 1; else hi = m;
    }
    return lo;
}

// block per graph; graph_ids sorted -> segment = [lb(g), lb(g+1))
__global__ void readout_kernel(const int* __restrict__ gids, int N) {
    int g = blockIdx.x;
    int t = threadIdx.x;
    int start = lower_bound_i(gids, N, g);
    int end   = lower_bound_i(gids, N, g + 1);
    if (t < HIDDEN) {
        float s = 0.0f;
        float m = 0.0f;   // relu output >= 0; empty graph -> 0 per reference
        for (int n = start; n < end; n++) {
            float v = d_h2[(size_t)n * HIDDEN + t];
            s += v * d_wnode[n];
            m = fmaxf(m, v);
        }
        d_gfeat[g * (2 * HIDDEN) + t]          = s;
        d_gfeat[g * (2 * HIDDEN) + HIDDEN + t] = m;
    }
}

// ---------------------------------------------------------------------------
// out[g] = (gfeat @ Wp1 + bp1) @ Wp2 + bp2   (64 hidden, no activation)
__global__ void mlp_kernel(const float* __restrict__ Wp1,
                           const float* __restrict__ bp1,
                           const float* __restrict__ Wp2,
                           const float* __restrict__ bp2,
                           float* __restrict__ out) {
    __shared__ float gf[2 * HIDDEN];
    __shared__ float partial[2];
    int g = blockIdx.x;
    int t = threadIdx.x;   // 64 threads
    for (int i = t; i < 2 * HIDDEN; i += 64) gf[i] = d_gfeat[g * (2 * HIDDEN) + i];
    __syncthreads();
    float acc = bp1[t];
    #pragma unroll 4
    for (int k = 0; k < 2 * HIDDEN; k++) acc += gf[k] * Wp1[k * 64 + t];
    float val = acc * Wp2[t];
    #pragma unroll
    for (int o = 16; o; o >>= 1) val += __shfl_xor_sync(0xFFFFFFFFu, val, o);
    if ((t & 31) == 0) partial[t >> 5] = val;
    __syncthreads();
    if (t == 0) out[g] = partial[0] + partial[1] + bp2[0];
}

// ---------------------------------------------------------------------------
extern "C" void kernel_launch(void* const* d_in, const int* in_sizes, int n_in,
                              void* d_out, int out_size) {
    const float* X    = (const float*)d_in[0];
    const int*   src  = (const int*)  d_in[1];
    const int*   dst  = (const int*)  d_in[2];
    const int*   gids = (const int*)  d_in[3];
    // d_in[4] = n_graphs (device scalar, unused; G = out_size)
    const float* Ws1 = (const float*)d_in[5];
    const float* Wn1 = (const float*)d_in[6];
    const float* b1  = (const float*)d_in[7];
    const float* Ws2 = (const float*)d_in[8];
    const float* Wn2 = (const float*)d_in[9];
    const float* b2  = (const float*)d_in[10];
    const float* wa  = (const float*)d_in[11];
    const float* ba  = (const float*)d_in[12];
    const float* Wp1 = (const float*)d_in[13];
    const float* bp1 = (const float*)d_in[14];
    const float* Wp2 = (const float*)d_in[15];
    const float* bp2 = (const float*)d_in[16];
    float* out = (float*)d_out;

    const int N   = in_sizes[3];
    const int E   = in_sizes[1];
    const int inF = in_sizes[0] / N;   // 74
    const int G   = out_size;          // 1024

    // 1. zero scratch
    zero_scratch<<<2048, 256>>>(N);
    // 2. pad X rows to float4 alignment
    pad_kernel<<<2048, 256>>>(X, N, inF);
    // 3. layer-1 edge aggregation (+degree): warp per edge, 8 warps per block
    {
        int blocks = (E + 7) / 8;
        scatter1_kernel<<<blocks, 256>>>(src, dst, E);
    }
    // 4. layer-1 fused GEMM
    sage_gemm_kernel<<<(N + BM - 1) / BM, 256>>>(0, N, inF, inF, Ws1, Wn1, b1);
    // 5. layer-2 edge aggregation
    {
        int blocks = (E + 7) / 8;
        scatter2_kernel<<<blocks, 256>>>(src, dst, E);
    }
    // 6. layer-2 fused GEMM
    sage_gemm_kernel<<<(N + BM - 1) / BM, 256>>>(1, N, HIDDEN, HIDDEN, Ws2, Wn2, b2);
    // 7. per-node sigmoid gate: warp per node
    {
        int blocks = (N + 7) / 8;
        wnode_kernel<<<blocks, 256>>>(wa, ba, N);
    }
    // 8. per-graph weighted sum + max
    readout_kernel<<<G, 128>>>(gids, N);
    // 9. predictor MLP
    mlp_kernel<<<G, 64>>>(Wp1, bp1, Wp2, bp2, out);
}

// round 5
// speedup vs baseline: 1.6427x; 1.3853x over previous
#include <cuda_runtime.h>
#include <cuda_bf16.h>
#include <math.h>

// ---------------------------------------------------------------------------
// GraphSAGE (2x SAGEConv mean) + WeightedSumAndMax readout + 2-layer MLP.
//
// R5: replace edge-scatter atomics (red.global.add.v4 = L2 RMW, ~420us) with a
// per-launch dst-CSR build + warp-per-node read-only gather aggregation:
//   zero_cnt, pad | hist -> scanA -> scanB -> scanC -> fill   (CSR build ~45us)
//   gather1 -> gemm1 -> gather2 -> gemm2 -> wnode -> readout -> mlp
// Degree comes from rowptr (no float atomics, no agg zeroing).
// GEMM kernels unchanged from R4 (measured 164us L2-layer) except invdeg read.
// ---------------------------------------------------------------------------

#define N_MAX   100000
#define E_MAX   1600000
#define FPAD    76          // 74 padded to 76 -> 19 float4 per row
#define HIDDEN  100         // 25 float4 per row
#define G_MAX   1024
#define NB_SCAN ((N_MAX + 1023) / 1024)   // 98 scan blocks

__device__ __align__(128) float d_Xpad [N_MAX * FPAD];
__device__ __align__(128) float d_agg1 [N_MAX * FPAD];
__device__ __align__(128) float d_h1   [N_MAX * HIDDEN];
__device__ __align__(128) float d_agg2 [N_MAX * HIDDEN];
__device__ __align__(128) float d_h2   [N_MAX * HIDDEN];
__device__ __align__(128) float d_wnode[N_MAX];
__device__ __align__(128) float d_gfeat[G_MAX * 2 * HIDDEN];
__device__ __align__(128) float d_invdeg[N_MAX];

// CSR scratch
__device__ __align__(128) int d_cnt    [N_MAX];
__device__ __align__(128) int d_scanTmp[N_MAX];
__device__ __align__(128) int d_bsum   [128];
__device__ __align__(128) int d_boff   [128];
__device__ __align__(128) int d_rowptr [N_MAX + 1];
__device__ __align__(128) int d_cursor [N_MAX];
__device__ __align__(128) int d_col    [E_MAX];

// ---------------------------------------------------------------------------
__global__ void zero_cnt_kernel(int N) {
    int i = blockIdx.x * blockDim.x + threadIdx.x;
    int stride = gridDim.x * blockDim.x;
    for (int idx = i; idx < N; idx += stride) d_cnt[idx] = 0;
}

__global__ void pad_kernel(const float* __restrict__ X, int N, int inF) {
    int i = blockIdx.x * blockDim.x + threadIdx.x;
    int stride = gridDim.x * blockDim.x;
    int total = N * FPAD;
    for (int idx = i; idx < total; idx += stride) {
        int n = idx / FPAD;
        int k = idx - n * FPAD;
        d_Xpad[idx] = (k < inF) ? X[(size_t)n * inF + k] : 0.0f;
    }
}

__global__ void hist_kernel(const int* __restrict__ dst, int E) {
    int i = blockIdx.x * blockDim.x + threadIdx.x;
    int stride = gridDim.x * blockDim.x;
    for (int e = i; e < E; e += stride) atomicAdd(&d_cnt[dst[e]], 1);
}

// inclusive scan of cnt in 1024-chunks; chunk totals to d_bsum
__global__ void scanA_kernel(int N) {
    __shared__ int sh[1024];
    int t = threadIdx.x;
    int g = blockIdx.x * 1024 + t;
    int v = (g < N) ? d_cnt[g] : 0;
    sh[t] = v;
    __syncthreads();
    #pragma unroll
    for (int o = 1; o < 1024; o <<= 1) {
        int a = (t >= o) ? sh[t - o] : 0;
        __syncthreads();
        sh[t] += a;
        __syncthreads();
    }
    if (g < N) d_scanTmp[g] = sh[t];
    if (t == 1023) d_bsum[blockIdx.x] = sh[1023];
}

// exclusive scan of the (<=128) chunk totals
__global__ void scanB_kernel(int nb) {
    __shared__ int sh[128];
    int t = threadIdx.x;
    int v = (t < nb) ? d_bsum[t] : 0;
    sh[t] = v;
    __syncthreads();
    #pragma unroll
    for (int o = 1; o < 128; o <<= 1) {
        int a = (t >= o) ? sh[t - o] : 0;
        __syncthreads();
        sh[t] += a;
        __syncthreads();
    }
    d_boff[t] = sh[t] - v;   // exclusive
}

// finalize rowptr / cursor / invdeg
__global__ void scanC_kernel(int N) {
    int i = blockIdx.x * blockDim.x + threadIdx.x;
    int stride = gridDim.x * blockDim.x;
    for (int idx = i; idx < N; idx += stride) {
        int incl = d_scanTmp[idx] + d_boff[idx >> 10];
        d_rowptr[idx + 1] = incl;
        int c = d_cnt[idx];
        d_cursor[idx] = incl - c;
        d_invdeg[idx] = 1.0f / fmaxf((float)c, 1.0f);
    }
    if (blockIdx.x == 0 && threadIdx.x == 0) d_rowptr[0] = 0;
}

__global__ void fill_kernel(const int* __restrict__ src,
                            const int* __restrict__ dst, int E) {
    int i = blockIdx.x * blockDim.x + threadIdx.x;
    int stride = gridDim.x * blockDim.x;
    for (int e = i; e < E; e += stride) {
        int d = dst[e];
        int slot = atomicAdd(&d_cursor[d], 1);
        d_col[slot] = src[e];
    }
}

// ---------------------------------------------------------------------------
// Gather aggregation: warp per node, lanes own one float4 column each,
// neighbors unrolled x2 for memory-level parallelism. Read-only (no RMW).
__global__ void gather1_kernel(int N) {
    int w    = (blockIdx.x * blockDim.x + threadIdx.x) >> 5;
    int lane = threadIdx.x & 31;
    if (w >= N) return;
    int beg = d_rowptr[w];
    int end = d_rowptr[w + 1];
    const float4* X4 = reinterpret_cast<const float4*>(d_Xpad);
    float4 acc = make_float4(0.f, 0.f, 0.f, 0.f);
    int i = beg;
    for (; i + 1 < end; i += 2) {
        int s0 = d_col[i];
        int s1 = d_col[i + 1];
        if (lane < FPAD / 4) {
            float4 a = X4[(size_t)s0 * (FPAD/4) + lane];
            float4 b = X4[(size_t)s1 * (FPAD/4) + lane];
            acc.x += a.x + b.x; acc.y += a.y + b.y;
            acc.z += a.z + b.z; acc.w += a.w + b.w;
        }
    }
    if (i < end) {
        int s = d_col[i];
        if (lane < FPAD / 4) {
            float4 a = X4[(size_t)s * (FPAD/4) + lane];
            acc.x += a.x; acc.y += a.y; acc.z += a.z; acc.w += a.w;
        }
    }
    if (lane < FPAD / 4)
        reinterpret_cast<float4*>(d_agg1)[(size_t)w * (FPAD/4) + lane] = acc;
}

__global__ void gather2_kernel(int N) {
    int w    = (blockIdx.x * blockDim.x + threadIdx.x) >> 5;
    int lane = threadIdx.x & 31;
    if (w >= N) return;
    int beg = d_rowptr[w];
    int end = d_rowptr[w + 1];
    const float4* H4 = reinterpret_cast<const float4*>(d_h1);
    float4 acc = make_float4(0.f, 0.f, 0.f, 0.f);
    int i = beg;
    for (; i + 1 < end; i += 2) {
        int s0 = d_col[i];
        int s1 = d_col[i + 1];
        if (lane < HIDDEN / 4) {
            float4 a = H4[(size_t)s0 * (HIDDEN/4) + lane];
            float4 b = H4[(size_t)s1 * (HIDDEN/4) + lane];
            acc.x += a.x + b.x; acc.y += a.y + b.y;
            acc.z += a.z + b.z; acc.w += a.w + b.w;
        }
    }
    if (i < end) {
        int s = d_col[i];
        if (lane < HIDDEN / 4) {
            float4 a = H4[(size_t)s * (HIDDEN/4) + lane];
            acc.x += a.x; acc.y += a.y; acc.z += a.z; acc.w += a.w;
        }
    }
    if (lane < HIDDEN / 4)
        reinterpret_cast<float4*>(d_agg2)[(size_t)w * (HIDDEN/4) + lane] = acc;
}

// ---------------------------------------------------------------------------
// Fused SAGE layer GEMM (R4 shape, measured 164us for layer 2):
//   out[n][c] = relu( sum_k A[n][k] * Wcat[k][c] + b[c] )
// BM=40 nodes x 100 cols per block; 250 threads each own a 4-node x 4-col tile.
// ---------------------------------------------------------------------------
#define KC   25
#define BM   40
#define AST  44   // a_s row stride in floats: 176B = 16B multiple

__global__ __launch_bounds__(256, 6)
void sage_gemm_kernel(int layer, int N, int Fs, int Fn,
                      const float* __restrict__ Wself,
                      const float* __restrict__ Wneigh,
                      const float* __restrict__ bias) {
    __shared__ __align__(16) float w_s[KC * HIDDEN];   // [kl][c]  25x100
    __shared__ __align__(16) float a_s[KC * AST];      // [kl][n]  25x44 (40 used)
    __shared__ __align__(16) float invd_s[BM];

    const float* Xs  = (layer == 0) ? d_Xpad : d_h1;
    const float* Agg = (layer == 0) ? d_agg1 : d_agg2;
    float*       Out = (layer == 0) ? d_h1   : d_h2;
    const int    ldS = (layer == 0) ? FPAD   : HIDDEN;

    const int tid  = threadIdx.x;
    const int base = blockIdx.x * BM;
    const int Ktot = Fs + Fn;
    const int nchunks = (Ktot + KC - 1) / KC;

    if (tid < BM) {
        int n = base + tid;
        invd_s[tid] = (n < N) ? d_invdeg[n] : 1.0f;
    }
    __syncthreads();

    const int cg = tid % 25;          // cols 4*cg .. 4*cg+3
    const int ng = tid / 25;          // nodes 4*ng .. 4*ng+3 (ng<10 for tid<250)
    const bool active = (tid < 250);

    float acc[4][4];
    #pragma unroll
    for (int i = 0; i < 4; i++)
        #pragma unroll
        for (int j = 0; j < 4; j++) acc[i][j] = 0.0f;

    const float4* a4p = reinterpret_cast<const float4*>(a_s) + ng;
    const float4* w4p = reinterpret_cast<const float4*>(w_s) + cg;

    for (int ch = 0; ch < nchunks; ch++) {
        int k0 = ch * KC;

        for (int idx = tid; idx < KC * BM; idx += 256) {
            int n  = idx / KC;
            int kl = idx - n * KC;
            int kg = k0 + kl;
            int gn = base + n;
            float v = 0.0f;
            if (gn < N) {
                if (kg < Fs)        v = Xs[(size_t)gn * ldS + kg];
                else if (kg < Ktot) v = Agg[(size_t)gn * ldS + (kg - Fs)] * invd_s[n];
            }
            a_s[kl * AST + n] = v;
        }
        for (int idx = tid; idx < KC * HIDDEN; idx += 256) {
            int kl = idx / HIDDEN;
            int c  = idx - kl * HIDDEN;
            int kg = k0 + kl;
            float v = 0.0f;
            if (kg < Fs)        v = Wself[kg * HIDDEN + c];
            else if (kg < Ktot) v = Wneigh[(kg - Fs) * HIDDEN + c];
            w_s[idx] = v;
        }
        __syncthreads();

        if (active) {
            #pragma unroll 5
            for (int kl = 0; kl < KC; kl++) {
                float4 a4 = a4p[kl * (AST / 4)];
                float4 w4 = w4p[kl * (HIDDEN / 4)];
                acc[0][0] += a4.x * w4.x; acc[0][1] += a4.x * w4.y; acc[0][2] += a4.x * w4.z; acc[0][3] += a4.x * w4.w;
                acc[1][0] += a4.y * w4.x; acc[1][1] += a4.y * w4.y; acc[1][2] += a4.y * w4.z; acc[1][3] += a4.y * w4.w;
                acc[2][0] += a4.z * w4.x; acc[2][1] += a4.z * w4.y; acc[2][2] += a4.z * w4.z; acc[2][3] += a4.z * w4.w;
                acc[3][0] += a4.w * w4.x; acc[3][1] += a4.w * w4.y; acc[3][2] += a4.w * w4.z; acc[3][3] += a4.w * w4.w;
            }
        }
        __syncthreads();
    }

    if (active) {
        float b[4];
        #pragma unroll
        for (int j = 0; j < 4; j++) b[j] = bias[4 * cg + j];
        #pragma unroll
        for (int i = 0; i < 4; i++) {
            int n = base + 4 * ng + i;
            if (n < N) {
                float4 o;
                o.x = fmaxf(acc[i][0] + b[0], 0.0f);
                o.y = fmaxf(acc[i][1] + b[1], 0.0f);
                o.z = fmaxf(acc[i][2] + b[2], 0.0f);
                o.w = fmaxf(acc[i][3] + b[3], 0.0f);
                reinterpret_cast<float4*>(Out + (size_t)n * HIDDEN)[cg] = o;
            }
        }
    }
}

// ---------------------------------------------------------------------------
// w[n] = sigmoid(h2[n] . w_atom + b_atom) — warp per node
__global__ void wnode_kernel(const float* __restrict__ w_atom,
                             const float* __restrict__ b_atom, int N) {
    int gid  = blockIdx.x * blockDim.x + threadIdx.x;
    int n    = gid >> 5;
    int lane = gid & 31;
    if (n >= N) return;
    float s = 0.0f;
    for (int k = lane; k < HIDDEN; k += 32)
        s += d_h2[(size_t)n * HIDDEN + k] * w_atom[k];
    #pragma unroll
    for (int o = 16; o; o >>= 1) s += __shfl_xor_sync(0xFFFFFFFFu, s, o);
    if (lane == 0) d_wnode[n] = 1.0f / (1.0f + expf(-(s + b_atom[0])));
}

// ---------------------------------------------------------------------------
__device__ __forceinline__ int lower_bound_i(const int* __restrict__ a, int n, int key) {
    int lo = 0, hi = n;
    while (lo < hi) {
        int m = (lo + hi) >> 1;
        if (a[m] < key) lo = m + 1; else hi = m;
    }
    return lo;
}

// block per graph; graph_ids sorted -> segment = [lb(g), lb(g+1))
__global__ void readout_kernel(const int* __restrict__ gids, int N) {
    int g = blockIdx.x;
    int t = threadIdx.x;
    int start = lower_bound_i(gids, N, g);
    int end   = lower_bound_i(gids, N, g + 1);
    if (t < HIDDEN) {
        float s = 0.0f;
        float m = 0.0f;   // relu output >= 0; empty graph -> 0 per reference
        for (int n = start; n < end; n++) {
            float v = d_h2[(size_t)n * HIDDEN + t];
            s += v * d_wnode[n];
            m = fmaxf(m, v);
        }
        d_gfeat[g * (2 * HIDDEN) + t]          = s;
        d_gfeat[g * (2 * HIDDEN) + HIDDEN + t] = m;
    }
}

// ---------------------------------------------------------------------------
// out[g] = (gfeat @ Wp1 + bp1) @ Wp2 + bp2   (64 hidden, no activation)
__global__ void mlp_kernel(const float* __restrict__ Wp1,
                           const float* __restrict__ bp1,
                           const float* __restrict__ Wp2,
                           const float* __restrict__ bp2,
                           float* __restrict__ out) {
    __shared__ float gf[2 * HIDDEN];
    __shared__ float partial[2];
    int g = blockIdx.x;
    int t = threadIdx.x;   // 64 threads
    for (int i = t; i < 2 * HIDDEN; i += 64) gf[i] = d_gfeat[g * (2 * HIDDEN) + i];
    __syncthreads();
    float acc = bp1[t];
    #pragma unroll 4
    for (int k = 0; k < 2 * HIDDEN; k++) acc += gf[k] * Wp1[k * 64 + t];
    float val = acc * Wp2[t];
    #pragma unroll
    for (int o = 16; o; o >>= 1) val += __shfl_xor_sync(0xFFFFFFFFu, val, o);
    if ((t & 31) == 0) partial[t >> 5] = val;
    __syncthreads();
    if (t == 0) out[g] = partial[0] + partial[1] + bp2[0];
}

// ---------------------------------------------------------------------------
extern "C" void kernel_launch(void* const* d_in, const int* in_sizes, int n_in,
                              void* d_out, int out_size) {
    const float* X    = (const float*)d_in[0];
    const int*   src  = (const int*)  d_in[1];
    const int*   dst  = (const int*)  d_in[2];
    const int*   gids = (const int*)  d_in[3];
    // d_in[4] = n_graphs (device scalar, unused; G = out_size)
    const float* Ws1 = (const float*)d_in[5];
    const float* Wn1 = (const float*)d_in[6];
    const float* b1  = (const float*)d_in[7];
    const float* Ws2 = (const float*)d_in[8];
    const float* Wn2 = (const float*)d_in[9];
    const float* b2  = (const float*)d_in[10];
    const float* wa  = (const float*)d_in[11];
    const float* ba  = (const float*)d_in[12];
    const float* Wp1 = (const float*)d_in[13];
    const float* bp1 = (const float*)d_in[14];
    const float* Wp2 = (const float*)d_in[15];
    const float* bp2 = (const float*)d_in[16];
    float* out = (float*)d_out;

    const int N   = in_sizes[3];
    const int E   = in_sizes[1];
    const int inF = in_sizes[0] / N;   // 74
    const int G   = out_size;          // 1024
    const int nb  = (N + 1023) / 1024;

    // CSR build + input padding
    zero_cnt_kernel<<<256, 256>>>(N);
    pad_kernel<<<2048, 256>>>(X, N, inF);
    hist_kernel<<<1024, 256>>>(dst, E);
    scanA_kernel<<<nb, 1024>>>(N);
    scanB_kernel<<<1, 128>>>(nb);
    scanC_kernel<<<256, 256>>>(N);
    fill_kernel<<<1024, 256>>>(src, dst, E);

    // layer 1: gather + fused GEMM
    gather1_kernel<<<(N + 7) / 8, 256>>>(N);
    sage_gemm_kernel<<<(N + BM - 1) / BM, 256>>>(0, N, inF, inF, Ws1, Wn1, b1);

    // layer 2: gather + fused GEMM
    gather2_kernel<<<(N + 7) / 8, 256>>>(N);
    sage_gemm_kernel<<<(N + BM - 1) / BM, 256>>>(1, N, HIDDEN, HIDDEN, Ws2, Wn2, b2);

    // readout + predictor
    wnode_kernel<<<(N + 7) / 8, 256>>>(wa, ba, N);
    readout_kernel<<<G, 128>>>(gids, N);
    mlp_kernel<<<G, 64>>>(Wp1, bp1, Wp2, bp2, out);
}